// round 5
// baseline (speedup 1.0000x reference)
#include <cuda_runtime.h>
#include <cuda_fp16.h>
#include <stdint.h>

#define DEVI static __device__ __forceinline__

#define BATCH 512
#define DIM   512
#define NCLS  100000
#define NTILES 782            // ceil(100000/128)

static constexpr float C_SCALE  = 64.0f;
static constexpr float C_ALPHA  = 1.2f;
static constexpr float C_COSM   =  0.87758256189037271612f;  // cos(0.5)
static constexpr float C_SINM   =  0.47942553860420300027f;  // sin(0.5)
static constexpr float C_THRESH = -0.87758256189037271612f;  // cos(pi-0.5)
static constexpr float C_MM     =  0.23971276930210150013f;  // sin(0.5)*0.5

// ---- device-global scratch (no allocation allowed) ----
__device__ __align__(1024) __half g_Ah[BATCH * DIM];
__device__ __align__(1024) __half g_Bh[(size_t)NCLS * DIM];
__device__ float g_target[BATCH];
__device__ int   g_label[BATCH];

// ---------------- PTX helpers ----------------
DEVI uint32_t smem_u32(const void* p) {
    uint32_t a;
    asm("{ .reg .u64 t; cvta.to.shared.u64 t, %1; cvt.u32.u64 %0, t; }" : "=r"(a) : "l"(p));
    return a;
}
DEVI void cp_async16(uint32_t dst, const void* src) {
    asm volatile("cp.async.cg.shared.global [%0], [%1], 16;" :: "r"(dst), "l"(src) : "memory");
}
DEVI void cp_commit() { asm volatile("cp.async.commit_group;" ::: "memory"); }
template <int N> DEVI void cp_wait() {
    asm volatile("cp.async.wait_group %0;" :: "n"(N) : "memory");
}
DEVI void ldsm_x4(uint32_t* r, uint32_t addr) {
    asm volatile("ldmatrix.sync.aligned.m8n8.x4.shared.b16 {%0,%1,%2,%3}, [%4];"
                 : "=r"(r[0]), "=r"(r[1]), "=r"(r[2]), "=r"(r[3]) : "r"(addr));
}
DEVI void mma16816(float* d, const uint32_t* a, uint32_t b0, uint32_t b1) {
    asm volatile(
        "mma.sync.aligned.m16n8k16.row.col.f32.f16.f16.f32 "
        "{%0,%1,%2,%3}, {%4,%5,%6,%7}, {%8,%9}, {%0,%1,%2,%3};"
        : "+f"(d[0]), "+f"(d[1]), "+f"(d[2]), "+f"(d[3])
        : "r"(a[0]), "r"(a[1]), "r"(a[2]), "r"(a[3]), "r"(b0), "r"(b1));
}

// ---------------- kernel 0: canonicalize label dtype (int32 vs int64) ----------------
// If the buffer is int64, every odd int32 word is the zero high-half (labels are
// nonneg < 2^31). If int32, odd words are random labels; OR over 256 of them is
// nonzero with overwhelming probability.
__global__ void label_fix_kernel(const int* __restrict__ lraw)
{
    __shared__ int s_or;
    const int tid = threadIdx.x;   // 512 threads
    if (tid == 0) s_or = 0;
    __syncthreads();
    if (tid < 256) {
        if (lraw[2 * tid + 1] != 0) atomicOr(&s_or, 1);
    }
    __syncthreads();
    if (s_or) g_label[tid] = lraw[tid];        // int32
    else      g_label[tid] = lraw[2 * tid];    // int64 low word
}

// ---------------- kernel 1: row-normalize + fp16 convert ----------------
// one warp per row (512 floats), 8 warps/block.
// NOTE: destination selected in DEVICE code — __device__ globals must never be
// passed as kernel args from host (host-side symbol address is garbage).
__global__ void norm_kernel(const float* __restrict__ src, int isA, int nrows)
{
    __half* __restrict__ dst = isA ? g_Ah : g_Bh;
    const int row  = blockIdx.x * 8 + (threadIdx.x >> 5);
    const int lane = threadIdx.x & 31;
    if (row >= nrows) return;

    const float4* sp = (const float4*)(src + (size_t)row * DIM);
    float4 v[4];
    float ss = 0.f;
#pragma unroll
    for (int i = 0; i < 4; i++) {
        v[i] = sp[lane + 32 * i];
        ss += v[i].x * v[i].x + v[i].y * v[i].y + v[i].z * v[i].z + v[i].w * v[i].w;
    }
#pragma unroll
    for (int o = 16; o > 0; o >>= 1) ss += __shfl_xor_sync(0xFFFFFFFFu, ss, o);

    float r = rsqrtf(ss);
    r = r * (1.5f - 0.5f * ss * r * r);   // NR refine -> ~fp32 exact

    uint2* dp = (uint2*)(dst + (size_t)row * DIM);
#pragma unroll
    for (int i = 0; i < 4; i++) {
        __half h0 = __float2half_rn(v[i].x * r);
        __half h1 = __float2half_rn(v[i].y * r);
        __half h2 = __float2half_rn(v[i].z * r);
        __half h3 = __float2half_rn(v[i].w * r);
        __half2 p01 = __halves2half2(h0, h1);
        __half2 p23 = __halves2half2(h2, h3);
        uint2 u;
        u.x = *(uint32_t*)&p01;
        u.y = *(uint32_t*)&p23;
        dp[lane + 32 * i] = u;
    }
}

// ---------------- kernel 2: exact fp32 per-row margined target ----------------
__global__ void target_kernel(const float* __restrict__ x,
                              const float* __restrict__ w)
{
    const int b    = blockIdx.x * 8 + (threadIdx.x >> 5);
    const int lane = threadIdx.x & 31;
    if (b >= BATCH) return;
    const int lb = g_label[b];

    const float4* xp = (const float4*)(x + (size_t)b * DIM);
    const float4* wp = (const float4*)(w + (size_t)lb * DIM);
    float xx = 0.f, ww = 0.f, xw = 0.f;
#pragma unroll
    for (int i = 0; i < 4; i++) {
        float4 a = xp[lane + 32 * i];
        float4 c = wp[lane + 32 * i];
        xx += a.x * a.x + a.y * a.y + a.z * a.z + a.w * a.w;
        ww += c.x * c.x + c.y * c.y + c.z * c.z + c.w * c.w;
        xw += a.x * c.x + a.y * c.y + a.z * c.z + a.w * c.w;
    }
#pragma unroll
    for (int o = 16; o > 0; o >>= 1) {
        xx += __shfl_xor_sync(0xFFFFFFFFu, xx, o);
        ww += __shfl_xor_sync(0xFFFFFFFFu, ww, o);
        xw += __shfl_xor_sync(0xFFFFFFFFu, xw, o);
    }
    if (lane == 0) {
        float p = xx * ww;
        float r = rsqrtf(p);
        r = r * (1.5f - 0.5f * p * r * r);
        float c = xw * r;
        float tgt = (c > C_THRESH)
                        ? (c * C_COSM - C_SINM * sqrtf(fmaxf(1.f - c * c, 0.f)))
                        : (c - C_MM);
        g_target[b] = tgt;
    }
}

// ---------------- kernel 3: mma.sync GEMM + fused ArcNegFace epilogue ----------------
// CTA tile 128M x 128N, K chunks of 64, double-buffered cp.async.
// 8 warps: warp tile 64M x 32N  (wm = (wid&1)*64, wn = (wid>>1)*32)
// SMEM: A [2][128][64] fp16 @ 0 (16KB/buf), B [2][128][64] fp16 @ 32768.
__global__ __launch_bounds__(256)
void gemm_kernel(float* __restrict__ out)
{
    extern __shared__ char smem[];
    const uint32_t sbase = smem_u32(smem);
    const int tid  = threadIdx.x;
    const int wid  = tid >> 5;
    const int lane = tid & 31;
    const int m0   = blockIdx.x * 128;   // 4 m-tiles, fastest -> share B tile in L2
    const int n0   = blockIdx.y * 128;
    const int wm   = (wid & 1) * 64;
    const int wn   = (wid >> 1) * 32;

    const char* Ag = (const char*)g_Ah;
    const char* Bg = (const char*)g_Bh;

    float acc[4][4][4];
#pragma unroll
    for (int mt = 0; mt < 4; mt++)
#pragma unroll
        for (int nt = 0; nt < 4; nt++)
#pragma unroll
            for (int i = 0; i < 4; i++) acc[mt][nt][i] = 0.f;

    // ---- async loader for one K-chunk into buffer `buf` ----
    auto load_chunk = [&](int buf, int kc) {
        const uint32_t sA = sbase + buf * 16384;
        const uint32_t sB = sbase + 32768 + buf * 16384;
#pragma unroll
        for (int it = 0; it < 4; it++) {
            int u = tid + 256 * it;          // 1024 granules of 16B
            int row = u >> 3;
            int c   = u & 7;
            uint32_t soff = (uint32_t)(row * 128 + ((c ^ (row & 7)) << 4));
            // A: rows m0+row, cols kc*64 + c*8 halves
            cp_async16(sA + soff, Ag + ((size_t)(m0 + row) * 512 + kc * 64 + c * 8) * 2);
            // B: rows n0+row (clamped), same cols
            int gr = n0 + row; if (gr >= NCLS) gr = NCLS - 1;
            cp_async16(sB + soff, Bg + ((size_t)gr * 512 + kc * 64 + c * 8) * 2);
        }
        cp_commit();
    };

    load_chunk(0, 0);

    for (int kc = 0; kc < 8; kc++) {
        const int cur = kc & 1;
        if (kc < 7) load_chunk(cur ^ 1, kc + 1);
        if (kc < 7) cp_wait<1>(); else cp_wait<0>();
        __syncthreads();

        const uint32_t sA = sbase + cur * 16384;
        const uint32_t sB = sbase + 32768 + cur * 16384;
#pragma unroll
        for (int ks = 0; ks < 4; ks++) {
            uint32_t a[4][4];
#pragma unroll
            for (int mt = 0; mt < 4; mt++) {
                int row = wm + mt * 16 + (lane & 15);
                int gr  = ks * 2 + (lane >> 4);
                ldsm_x4(a[mt], sA + row * 128 + (((uint32_t)gr ^ (row & 7)) << 4));
            }
            uint32_t b[2][4];
#pragma unroll
            for (int p = 0; p < 2; p++) {
                int nr = wn + p * 16 + (lane & 7) + ((lane >> 4) << 3);
                int gr = ks * 2 + ((lane >> 3) & 1);
                ldsm_x4(b[p], sB + nr * 128 + (((uint32_t)gr ^ (nr & 7)) << 4));
            }
#pragma unroll
            for (int mt = 0; mt < 4; mt++)
#pragma unroll
                for (int nt = 0; nt < 4; nt++)
                    mma16816(acc[mt][nt], a[mt], b[nt >> 1][(nt & 1) * 2],
                             b[nt >> 1][(nt & 1) * 2 + 1]);
        }
        __syncthreads();
    }

    // ---- fused ArcNegFace epilogue ----
#pragma unroll
    for (int mt = 0; mt < 4; mt++) {
        const int r0 = m0 + wm + mt * 16 + (lane >> 2);   // row half 0
        const int r1 = r0 + 8;                            // row half 1
        const float tg0 = g_target[r0], tg1 = g_target[r1];
        const int lb0 = g_label[r0],  lb1 = g_label[r1];
        float* o0 = out + (size_t)r0 * NCLS;
        float* o1 = out + (size_t)r1 * NCLS;
#pragma unroll
        for (int nt = 0; nt < 4; nt++) {
            const int c0 = n0 + wn + nt * 8 + 2 * (lane & 3);
            if (c0 >= NCLS) continue;   // NCLS even, c0 even -> pair all-or-nothing
            float v[4];
#pragma unroll
            for (int i = 0; i < 4; i++) {
                const float cs  = acc[mt][nt][i];
                const float tg  = (i < 2) ? tg0 : tg1;
                const int   lb  = (i < 2) ? lb0 : lb1;
                const float dd  = cs - tg;
                const float ts  = C_ALPHA * __expf(-0.5f * dd * dd);
                float r = C_SCALE * (ts * cs + ts - 1.0f);
                if (c0 + (i & 1) == lb) r = C_SCALE * tg;
                v[i] = r;
            }
            *(float2*)(o0 + c0) = make_float2(v[0], v[1]);
            *(float2*)(o1 + c0) = make_float2(v[2], v[3]);
        }
    }
}

// ---------------- launcher ----------------
extern "C" void kernel_launch(void* const* d_in, const int* in_sizes, int n_in,
                              void* d_out, int out_size)
{
    const float* x     = (const float*)d_in[0];
    const int*   lraw  = (const int*)d_in[1];
    const float* w     = (const float*)d_in[2];
    float*       out   = (float*)d_out;

    cudaFuncSetAttribute(gemm_kernel, cudaFuncAttributeMaxDynamicSharedMemorySize, 65536);

    label_fix_kernel<<<1, BATCH>>>(lraw);
    norm_kernel<<<BATCH / 8, 256>>>(x, 1, BATCH);
    norm_kernel<<<NCLS / 8, 256>>>(w, 0, NCLS);
    target_kernel<<<BATCH / 8, 256>>>(x, w);

    dim3 grid(4, NTILES);
    gemm_kernel<<<grid, 256, 65536>>>(out);
}

// round 6
// speedup vs baseline: 1.0172x; 1.0172x over previous
#include <cuda_runtime.h>
#include <cuda_fp16.h>
#include <stdint.h>

#define DEVI static __device__ __forceinline__

#define BATCH 512
#define DIM   512
#define NCLS  100000
#define NTILES 782            // ceil(100000/128)

static constexpr float C_SCALE  = 64.0f;
static constexpr float C_ALPHA  = 1.2f;
static constexpr float C_COSM   =  0.87758256189037271612f;  // cos(0.5)
static constexpr float C_SINM   =  0.47942553860420300027f;  // sin(0.5)
static constexpr float C_THRESH = -0.87758256189037271612f;  // cos(pi-0.5)
static constexpr float C_MM     =  0.23971276930210150013f;  // sin(0.5)*0.5

// ---- device-global scratch (no allocation allowed) ----
__device__ __align__(1024) __half g_Ah[BATCH * DIM];
__device__ __align__(1024) __half g_Bh[(size_t)NCLS * DIM];
__device__ float g_target[BATCH];
__device__ int   g_label[BATCH];

// ---------------- PTX helpers ----------------
DEVI uint32_t smem_u32(const void* p) {
    uint32_t a;
    asm("{ .reg .u64 t; cvta.to.shared.u64 t, %1; cvt.u32.u64 %0, t; }" : "=r"(a) : "l"(p));
    return a;
}
DEVI void cp_async16(uint32_t dst, const void* src) {
    asm volatile("cp.async.cg.shared.global [%0], [%1], 16;" :: "r"(dst), "l"(src) : "memory");
}
DEVI void cp_commit() { asm volatile("cp.async.commit_group;" ::: "memory"); }
template <int N> DEVI void cp_wait() {
    asm volatile("cp.async.wait_group %0;" :: "n"(N) : "memory");
}
DEVI void ldsm_x4(uint32_t* r, uint32_t addr) {
    asm volatile("ldmatrix.sync.aligned.m8n8.x4.shared.b16 {%0,%1,%2,%3}, [%4];"
                 : "=r"(r[0]), "=r"(r[1]), "=r"(r[2]), "=r"(r[3]) : "r"(addr));
}
DEVI void mma16816(float* d, const uint32_t* a, uint32_t b0, uint32_t b1) {
    asm volatile(
        "mma.sync.aligned.m16n8k16.row.col.f32.f16.f16.f32 "
        "{%0,%1,%2,%3}, {%4,%5,%6,%7}, {%8,%9}, {%0,%1,%2,%3};"
        : "+f"(d[0]), "+f"(d[1]), "+f"(d[2]), "+f"(d[3])
        : "r"(a[0]), "r"(a[1]), "r"(a[2]), "r"(a[3]), "r"(b0), "r"(b1));
}

// ---------------- kernel 1: prep (label fix + norm_x + exact target) ----------------
// grid 64, block 256. Each block handles 8 batch rows (one per warp).
// Label dtype detect per block: if buffer is int64, every odd int32 word is the
// zero high-half (labels nonneg < 2^31); if int32, odd words are random labels.
__global__ void prep_kernel(const float* __restrict__ x,
                            const int* __restrict__ lraw,
                            const float* __restrict__ w)
{
    __shared__ int s_or;
    const int tid  = threadIdx.x;
    const int wid  = tid >> 5;
    const int lane = tid & 31;
    const int b    = blockIdx.x * 8 + wid;

    if (tid == 0) s_or = 0;
    __syncthreads();
    if (tid < 256) {
        if (lraw[2 * tid + 1] != 0) atomicOr(&s_or, 1);
    }
    __syncthreads();
    const int lb = s_or ? lraw[b] : lraw[2 * b];
    if (lane == 0) g_label[b] = lb;

    // load x row, compute norms + dot with w[lb]
    const float4* xp = (const float4*)(x + (size_t)b * DIM);
    const float4* wp = (const float4*)(w + (size_t)lb * DIM);
    float4 v[4];
    float xx = 0.f, ww = 0.f, xw = 0.f;
#pragma unroll
    for (int i = 0; i < 4; i++) {
        v[i] = xp[lane + 32 * i];
        float4 c = wp[lane + 32 * i];
        xx += v[i].x * v[i].x + v[i].y * v[i].y + v[i].z * v[i].z + v[i].w * v[i].w;
        ww += c.x * c.x + c.y * c.y + c.z * c.z + c.w * c.w;
        xw += v[i].x * c.x + v[i].y * c.y + v[i].z * c.z + v[i].w * c.w;
    }
#pragma unroll
    for (int o = 16; o > 0; o >>= 1) {
        xx += __shfl_xor_sync(0xFFFFFFFFu, xx, o);
        ww += __shfl_xor_sync(0xFFFFFFFFu, ww, o);
        xw += __shfl_xor_sync(0xFFFFFFFFu, xw, o);
    }

    // normalized fp16 x row
    float rx = rsqrtf(xx);
    rx = rx * (1.5f - 0.5f * xx * rx * rx);
    uint2* dp = (uint2*)(g_Ah + (size_t)b * DIM);
#pragma unroll
    for (int i = 0; i < 4; i++) {
        __half h0 = __float2half_rn(v[i].x * rx);
        __half h1 = __float2half_rn(v[i].y * rx);
        __half h2 = __float2half_rn(v[i].z * rx);
        __half h3 = __float2half_rn(v[i].w * rx);
        __half2 p01 = __halves2half2(h0, h1);
        __half2 p23 = __halves2half2(h2, h3);
        uint2 u;
        u.x = *(uint32_t*)&p01;
        u.y = *(uint32_t*)&p23;
        dp[lane + 32 * i] = u;
    }

    // exact fp32 margined target
    if (lane == 0) {
        float p = xx * ww;
        float r = rsqrtf(p);
        r = r * (1.5f - 0.5f * p * r * r);
        float c = xw * r;
        float tgt = (c > C_THRESH)
                        ? (c * C_COSM - C_SINM * sqrtf(fmaxf(1.f - c * c, 0.f)))
                        : (c - C_MM);
        g_target[b] = tgt;
    }
}

// ---------------- kernel 2: row-normalize w + fp16 convert ----------------
__global__ void norm_w_kernel(const float* __restrict__ src)
{
    const int row  = blockIdx.x * 8 + (threadIdx.x >> 5);
    const int lane = threadIdx.x & 31;
    if (row >= NCLS) return;

    const float4* sp = (const float4*)(src + (size_t)row * DIM);
    float4 v[4];
    float ss = 0.f;
#pragma unroll
    for (int i = 0; i < 4; i++) {
        v[i] = sp[lane + 32 * i];
        ss += v[i].x * v[i].x + v[i].y * v[i].y + v[i].z * v[i].z + v[i].w * v[i].w;
    }
#pragma unroll
    for (int o = 16; o > 0; o >>= 1) ss += __shfl_xor_sync(0xFFFFFFFFu, ss, o);

    float r = rsqrtf(ss);
    r = r * (1.5f - 0.5f * ss * r * r);

    uint2* dp = (uint2*)(g_Bh + (size_t)row * DIM);
#pragma unroll
    for (int i = 0; i < 4; i++) {
        __half h0 = __float2half_rn(v[i].x * r);
        __half h1 = __float2half_rn(v[i].y * r);
        __half h2 = __float2half_rn(v[i].z * r);
        __half h3 = __float2half_rn(v[i].w * r);
        __half2 p01 = __halves2half2(h0, h1);
        __half2 p23 = __halves2half2(h2, h3);
        uint2 u;
        u.x = *(uint32_t*)&p01;
        u.y = *(uint32_t*)&p23;
        dp[lane + 32 * i] = u;
    }
}

// ---------------- kernel 3: mma.sync GEMM + fused ArcNegFace epilogue ----------------
// CTA tile 128M x 128N, K chunks of 64, 3-stage cp.async pipeline, 1 sync/iter.
// 8 warps: warp tile 64M x 32N. SMEM per stage: A 16KB + B 16KB; 3 stages = 96KB.
__global__ __launch_bounds__(256)
void gemm_kernel(float* __restrict__ out)
{
    extern __shared__ char smem[];
    const uint32_t sbase = smem_u32(smem);
    const int tid  = threadIdx.x;
    const int wid  = tid >> 5;
    const int lane = tid & 31;
    const int m0   = blockIdx.x * 128;   // 4 m-tiles fastest -> share B tile in L2
    const int n0   = blockIdx.y * 128;
    const int wm   = (wid & 1) * 64;
    const int wn   = (wid >> 1) * 32;

    const char* Ag = (const char*)g_Ah;
    const char* Bg = (const char*)g_Bh;

    float acc[4][4][4];
#pragma unroll
    for (int mt = 0; mt < 4; mt++)
#pragma unroll
        for (int nt = 0; nt < 4; nt++)
#pragma unroll
            for (int i = 0; i < 4; i++) acc[mt][nt][i] = 0.f;

    // ---- async loader for one K-chunk into stage s ----
    auto load_chunk = [&](int s, int kc) {
        const uint32_t sA = sbase + s * 32768;
        const uint32_t sB = sA + 16384;
#pragma unroll
        for (int it = 0; it < 4; it++) {
            int u = tid + 256 * it;          // 1024 granules of 16B
            int row = u >> 3;
            int c   = u & 7;
            uint32_t soff = (uint32_t)(row * 128 + ((c ^ (row & 7)) << 4));
            cp_async16(sA + soff, Ag + ((size_t)(m0 + row) * 512 + kc * 64 + c * 8) * 2);
            int gr = n0 + row; if (gr >= NCLS) gr = NCLS - 1;
            cp_async16(sB + soff, Bg + ((size_t)gr * 512 + kc * 64 + c * 8) * 2);
        }
        cp_commit();
    };

    load_chunk(0, 0);
    load_chunk(1, 1);

    int stage = 0;
#pragma unroll 2
    for (int kc = 0; kc < 8; kc++) {
        if (kc < 7) cp_wait<1>(); else cp_wait<0>();
        __syncthreads();
        // prefetch 2 chunks ahead into the stage computed last iteration
        if (kc + 2 < 8) {
            int ns = stage + 2; if (ns >= 3) ns -= 3;
            load_chunk(ns, kc + 2);
        }

        const uint32_t sA = sbase + stage * 32768;
        const uint32_t sB = sA + 16384;
#pragma unroll
        for (int ks = 0; ks < 4; ks++) {
            uint32_t a[4][4];
#pragma unroll
            for (int mt = 0; mt < 4; mt++) {
                int row = wm + mt * 16 + (lane & 15);
                int gr  = ks * 2 + (lane >> 4);
                ldsm_x4(a[mt], sA + row * 128 + (((uint32_t)gr ^ (row & 7)) << 4));
            }
            uint32_t b[2][4];
#pragma unroll
            for (int p = 0; p < 2; p++) {
                int nr = wn + p * 16 + (lane & 7) + ((lane >> 4) << 3);
                int gr = ks * 2 + ((lane >> 3) & 1);
                ldsm_x4(b[p], sB + nr * 128 + (((uint32_t)gr ^ (nr & 7)) << 4));
            }
#pragma unroll
            for (int mt = 0; mt < 4; mt++)
#pragma unroll
                for (int nt = 0; nt < 4; nt++)
                    mma16816(acc[mt][nt], a[mt], b[nt >> 1][(nt & 1) * 2],
                             b[nt >> 1][(nt & 1) * 2 + 1]);
        }
        stage++; if (stage >= 3) stage = 0;
    }

    // ---- fused ArcNegFace epilogue ----
#pragma unroll
    for (int mt = 0; mt < 4; mt++) {
        const int r0 = m0 + wm + mt * 16 + (lane >> 2);   // row half 0
        const int r1 = r0 + 8;                            // row half 1
        const float tg0 = g_target[r0], tg1 = g_target[r1];
        const int lb0 = g_label[r0],  lb1 = g_label[r1];
        float* o0 = out + (size_t)r0 * NCLS;
        float* o1 = out + (size_t)r1 * NCLS;
#pragma unroll
        for (int nt = 0; nt < 4; nt++) {
            const int c0 = n0 + wn + nt * 8 + 2 * (lane & 3);
            if (c0 >= NCLS) continue;   // NCLS even, c0 even -> pair all-or-nothing
            float v[4];
#pragma unroll
            for (int i = 0; i < 4; i++) {
                const float cs  = acc[mt][nt][i];
                const float tg  = (i < 2) ? tg0 : tg1;
                const int   lb  = (i < 2) ? lb0 : lb1;
                const float dd  = cs - tg;
                const float ts  = C_ALPHA * __expf(-0.5f * dd * dd);
                float r = C_SCALE * (ts * cs + ts - 1.0f);
                if (c0 + (i & 1) == lb) r = C_SCALE * tg;
                v[i] = r;
            }
            *(float2*)(o0 + c0) = make_float2(v[0], v[1]);
            *(float2*)(o1 + c0) = make_float2(v[2], v[3]);
        }
    }
}

// ---------------- launcher (3 launches per call) ----------------
extern "C" void kernel_launch(void* const* d_in, const int* in_sizes, int n_in,
                              void* d_out, int out_size)
{
    const float* x     = (const float*)d_in[0];
    const int*   lraw  = (const int*)d_in[1];
    const float* w     = (const float*)d_in[2];
    float*       out   = (float*)d_out;

    cudaFuncSetAttribute(gemm_kernel, cudaFuncAttributeMaxDynamicSharedMemorySize, 98304);

    prep_kernel<<<BATCH / 8, 256>>>(x, lraw, w);
    norm_w_kernel<<<NCLS / 8, 256>>>(w);

    dim3 grid(4, NTILES);
    gemm_kernel<<<grid, 256, 98304>>>(out);
}